// round 3
// baseline (speedup 1.0000x reference)
#include <cuda_runtime.h>
#include <math.h>

// Problem constants (fixed by the dataset)
#define NP 200000
#define NA 200000
#define NE 2000000
#define H  64
#define DP 128
#define DA 64
#define OUTD 32

// ---------------------------------------------------------------------------
// Device scratch (no cudaMalloc allowed)
// ---------------------------------------------------------------------------
__device__ float g_featP[(size_t)NP * H];
__device__ float g_featA[(size_t)NA * H];
__device__ float g_xP[(size_t)NP * H];
__device__ float g_xA[(size_t)NA * H];
__device__ float g_x1P[NP];
__device__ float g_h1P[NP];
__device__ float g_w2P[NP];
__device__ float g_x1A[NA];
__device__ float g_h1A[NA];
__device__ float g_w2A[NA];
// CSR
__device__ int g_rptrP[NP + 1];
__device__ int g_rptrA[NA + 1];
__device__ int g_ctgt_pa[NE];
__device__ int g_ctgt_ap[NE];
__device__ int g_counts[NP + 1];
__device__ int g_cursor[NP + 1];
__device__ int g_bsums[256];

__device__ __forceinline__ float leaky02(float v) {
    return v > 0.0f ? v : 0.2f * v;
}

// ---------------------------------------------------------------------------
// CSR build kernels
// ---------------------------------------------------------------------------
__global__ void zero_int_kernel(int* p, int n) {
    int i = blockIdx.x * blockDim.x + threadIdx.x;
    if (i < n) p[i] = 0;
}

__global__ void hist_kernel(const int* __restrict__ src, int E, int* __restrict__ counts) {
    int i = blockIdx.x * blockDim.x + threadIdx.x;
    if (i < E) atomicAdd(&counts[src[i]], 1);
}

__global__ void block_sums_kernel(const int* __restrict__ c, int n, int* __restrict__ bs) {
    __shared__ int sd[1024];
    int i = blockIdx.x * 1024 + threadIdx.x;
    sd[threadIdx.x] = (i < n) ? c[i] : 0;
    __syncthreads();
    for (int o = 512; o; o >>= 1) {
        if (threadIdx.x < o) sd[threadIdx.x] += sd[threadIdx.x + o];
        __syncthreads();
    }
    if (threadIdx.x == 0) bs[blockIdx.x] = sd[0];
}

__global__ void scan_bs_kernel(int* bs, int nb) {
    __shared__ int s[256];
    int tid = threadIdx.x;
    int v = tid < nb ? bs[tid] : 0;
    s[tid] = v;
    __syncthreads();
    for (int o = 1; o < 256; o <<= 1) {
        int u = (tid >= o) ? s[tid - o] : 0;
        __syncthreads();
        s[tid] += u;
        __syncthreads();
    }
    if (tid < nb) bs[tid] = s[tid] - v;   // exclusive
}

__global__ void scan_final_kernel(const int* __restrict__ c, int n,
                                  const int* __restrict__ bs, int* __restrict__ rptr) {
    __shared__ int sd[1024];
    int i = blockIdx.x * 1024 + threadIdx.x;
    int v = (i < n) ? c[i] : 0;
    sd[threadIdx.x] = v;
    __syncthreads();
    for (int o = 1; o < 1024; o <<= 1) {
        int u = (threadIdx.x >= o) ? sd[threadIdx.x - o] : 0;
        __syncthreads();
        sd[threadIdx.x] += u;
        __syncthreads();
    }
    int excl = sd[threadIdx.x] - v + bs[blockIdx.x];
    if (i < n) rptr[i] = excl;
    if (i == n - 1) rptr[n] = excl + v;
}

__global__ void copy_int_kernel(const int* __restrict__ a, int* __restrict__ b, int n) {
    int i = blockIdx.x * blockDim.x + threadIdx.x;
    if (i < n) b[i] = a[i];
}

__global__ void scatter_kernel(const int* __restrict__ src, const int* __restrict__ tgt,
                               int E, int* __restrict__ cursor, int* __restrict__ ctgt) {
    int i = blockIdx.x * blockDim.x + threadIdx.x;
    if (i < E) {
        int s = src[i];
        int pos = atomicAdd(&cursor[s], 1);
        ctgt[pos] = tgt[i];
    }
}

// ---------------------------------------------------------------------------
// GEMM: Y[N, NOUT] = act(X[N, K] @ W[K, NOUT] + b)
// 256 threads; each thread: 2 rows x 8 cols. W staged in shared memory.
// ---------------------------------------------------------------------------
template<int K, int NOUT, bool RELU>
__global__ void __launch_bounds__(256)
gemm_kernel(const float* __restrict__ X, const float* __restrict__ W,
            const float* __restrict__ bias, float* __restrict__ Y, int N)
{
    constexpr int TPR = NOUT / 8;     // threads spanning the NOUT dim
    constexpr int RG  = 256 / TPR;    // row-groups per block
    constexpr int RPB = RG * 2;       // rows per block

    __shared__ float sW[K * NOUT];
    for (int i = threadIdx.x; i < K * NOUT; i += 256) sW[i] = W[i];
    __syncthreads();

    const int tg = threadIdx.x / TPR;
    const int cg = threadIdx.x % TPR;
    const int r0 = blockIdx.x * RPB + tg * 2;
    const int c0 = cg * 8;

    float acc[2][8];
    #pragma unroll
    for (int c = 0; c < 8; c++) {
        float bv = bias[c0 + c];
        acc[0][c] = bv;
        acc[1][c] = bv;
    }

    int rr[2];
    #pragma unroll
    for (int r = 0; r < 2; r++) {
        int q = r0 + r;
        rr[r] = q < N ? q : (N - 1);
    }

    #pragma unroll 2
    for (int k4 = 0; k4 < K / 4; k4++) {
        const int kb = k4 * 4;
        float wv[4][8];
        #pragma unroll
        for (int kk = 0; kk < 4; kk++) {
            float4 wa = *(const float4*)(&sW[(kb + kk) * NOUT + c0]);
            float4 wb = *(const float4*)(&sW[(kb + kk) * NOUT + c0 + 4]);
            wv[kk][0] = wa.x; wv[kk][1] = wa.y; wv[kk][2] = wa.z; wv[kk][3] = wa.w;
            wv[kk][4] = wb.x; wv[kk][5] = wb.y; wv[kk][6] = wb.z; wv[kk][7] = wb.w;
        }
        #pragma unroll
        for (int r = 0; r < 2; r++) {
            float4 xv = *(const float4*)(X + (size_t)rr[r] * K + kb);
            float xs[4] = {xv.x, xv.y, xv.z, xv.w};
            #pragma unroll
            for (int kk = 0; kk < 4; kk++)
                #pragma unroll
                for (int c = 0; c < 8; c++)
                    acc[r][c] += xs[kk] * wv[kk][c];
        }
    }

    #pragma unroll
    for (int r = 0; r < 2; r++) {
        int q = r0 + r;
        if (q < N) {
            #pragma unroll
            for (int c = 0; c < 8; c++)
                if (RELU) acc[r][c] = fmaxf(acc[r][c], 0.0f);
            float4 va = {acc[r][0], acc[r][1], acc[r][2], acc[r][3]};
            float4 vb = {acc[r][4], acc[r][5], acc[r][6], acc[r][7]};
            *(float4*)(Y + (size_t)q * NOUT + c0)     = va;
            *(float4*)(Y + (size_t)q * NOUT + c0 + 4) = vb;
        }
    }
}

// ---------------------------------------------------------------------------
// Node prep: one warp per node.
//   x1  = x . a1own, h1 = x . a2oth, w2 = exp(leaky(x1 + x.a2own))
// ---------------------------------------------------------------------------
__global__ void __launch_bounds__(256)
nodeprep_kernel(const float* __restrict__ X, int N,
                const float* __restrict__ a1, const float* __restrict__ a2own,
                const float* __restrict__ a2oth,
                float* __restrict__ x1o, float* __restrict__ h1o,
                float* __restrict__ w2o)
{
    int warp = (blockIdx.x * blockDim.x + threadIdx.x) >> 5;
    int lane = threadIdx.x & 31;
    if (warp >= N) return;

    float2 xv = *(const float2*)(X + (size_t)warp * H + lane * 2);
    float2 v1 = *(const float2*)(a1 + lane * 2);
    float2 v2 = *(const float2*)(a2own + lane * 2);
    float2 v3 = *(const float2*)(a2oth + lane * 2);

    float d1 = xv.x * v1.x + xv.y * v1.y;
    float d2 = xv.x * v2.x + xv.y * v2.y;
    float d3 = xv.x * v3.x + xv.y * v3.y;
    #pragma unroll
    for (int o = 16; o; o >>= 1) {
        d1 += __shfl_xor_sync(0xFFFFFFFFu, d1, o);
        d2 += __shfl_xor_sync(0xFFFFFFFFu, d2, o);
        d3 += __shfl_xor_sync(0xFFFFFFFFu, d3, o);
    }
    if (lane == 0) {
        x1o[warp] = d1;
        h1o[warp] = d3;
        w2o[warp] = __expf(leaky02(d1 + d2));
    }
}

// ---------------------------------------------------------------------------
// CSR aggregation + finalize: one warp per source node.
//   acc = w2*x + sum_e w1_e * hfeat[t_e];  div = w2 + sum w1
//   out = elu(acc / div)
// ---------------------------------------------------------------------------
__global__ void __launch_bounds__(256)
csr_agg_kernel(const int* __restrict__ rptr, const int* __restrict__ ctgt,
               const float* __restrict__ x, const float* __restrict__ x1,
               const float* __restrict__ w2arr, const float* __restrict__ h1,
               const float* __restrict__ hfeat,
               float* __restrict__ outfeat, int N)
{
    int s = (blockIdx.x * blockDim.x + threadIdx.x) >> 5;
    int lane = threadIdx.x & 31;
    if (s >= N) return;

    int beg = rptr[s];
    int end = rptr[s + 1];
    float x1s = x1[s];
    float w2  = w2arr[s];

    float2 xv = *(const float2*)(x + (size_t)s * H + lane * 2);
    float2 acc; acc.x = w2 * xv.x; acc.y = w2 * xv.y;
    float divv = w2;

    for (int base = beg; base < end; base += 32) {
        int myIdx = base + lane;
        int t = 0; float h1t = 0.0f;
        if (myIdx < end) {
            t = ctgt[myIdx];
            h1t = h1[t];
        }
        int cnt = min(32, end - base);
        for (int i = 0; i < cnt; i++) {
            int   tt  = __shfl_sync(0xFFFFFFFFu, t, i);
            float h1v = __shfl_sync(0xFFFFFFFFu, h1t, i);
            float w1 = __expf(leaky02(x1s + h1v));
            float2 hv = *(const float2*)(hfeat + (size_t)tt * H + lane * 2);
            acc.x += w1 * hv.x;
            acc.y += w1 * hv.y;
            divv  += w1;
        }
    }

    float inv = 1.0f / divv;
    float vx = acc.x * inv;
    float vy = acc.y * inv;
    vx = vx > 0.0f ? vx : (__expf(vx) - 1.0f);
    vy = vy > 0.0f ? vy : (__expf(vy) - 1.0f);
    float2 o; o.x = vx; o.y = vy;
    *(float2*)(outfeat + (size_t)s * H + lane * 2) = o;
}

// ---------------------------------------------------------------------------
// Launch
// ---------------------------------------------------------------------------
static void build_csr(const int* src, const int* tgt, int N, int E,
                      int* rptr, int* ctgt, int* counts, int* cursor, int* bsums)
{
    const int NB = (N + 1023) / 1024;
    zero_int_kernel<<<(N + 255) / 256, 256>>>(counts, N);
    hist_kernel<<<(E + 255) / 256, 256>>>(src, E, counts);
    block_sums_kernel<<<NB, 1024>>>(counts, N, bsums);
    scan_bs_kernel<<<1, 256>>>(bsums, NB);
    scan_final_kernel<<<NB, 1024>>>(counts, N, bsums, rptr);
    copy_int_kernel<<<(N + 255) / 256, 256>>>(rptr, cursor, N);
    scatter_kernel<<<(E + 255) / 256, 256>>>(src, tgt, E, cursor, ctgt);
}

extern "C" void kernel_launch(void* const* d_in, const int* in_sizes, int n_in,
                              void* d_out, int out_size)
{
    const float* x_P     = (const float*)d_in[0];
    const float* x_A     = (const float*)d_in[1];
    const int*   ei_pa   = (const int*)d_in[2];   // [2, E]: row0 = P idx (src), row1 = A idx (dst)
    const int*   ei_ap   = (const int*)d_in[3];   // [2, E]: row0 = A idx (src), row1 = P idx (dst)
    const float* fc1_P_w = (const float*)d_in[4];
    const float* fc1_P_b = (const float*)d_in[5];
    const float* fc1_A_w = (const float*)d_in[6];
    const float* fc1_A_b = (const float*)d_in[7];
    const float* fcs_w   = (const float*)d_in[8];
    const float* fcs_b   = (const float*)d_in[9];
    const float* a1_pa   = (const float*)d_in[10];
    const float* a2_pa   = (const float*)d_in[11];
    const float* a1_ap   = (const float*)d_in[12];
    const float* a2_ap   = (const float*)d_in[13];
    const float* fc2_w   = (const float*)d_in[14];
    const float* fc2_b   = (const float*)d_in[15];
    float* out = (float*)d_out;

    float *featP, *featA, *xP, *xA;
    float *x1P, *h1P, *w2P, *x1A, *h1A, *w2A;
    int *rptrP, *rptrA, *ctgt_pa, *ctgt_ap, *counts, *cursor, *bsums;
    cudaGetSymbolAddress((void**)&featP, g_featP);
    cudaGetSymbolAddress((void**)&featA, g_featA);
    cudaGetSymbolAddress((void**)&xP,    g_xP);
    cudaGetSymbolAddress((void**)&xA,    g_xA);
    cudaGetSymbolAddress((void**)&x1P,   g_x1P);
    cudaGetSymbolAddress((void**)&h1P,   g_h1P);
    cudaGetSymbolAddress((void**)&w2P,   g_w2P);
    cudaGetSymbolAddress((void**)&x1A,   g_x1A);
    cudaGetSymbolAddress((void**)&h1A,   g_h1A);
    cudaGetSymbolAddress((void**)&w2A,   g_w2A);
    cudaGetSymbolAddress((void**)&rptrP,   g_rptrP);
    cudaGetSymbolAddress((void**)&rptrA,   g_rptrA);
    cudaGetSymbolAddress((void**)&ctgt_pa, g_ctgt_pa);
    cudaGetSymbolAddress((void**)&ctgt_ap, g_ctgt_ap);
    cudaGetSymbolAddress((void**)&counts,  g_counts);
    cudaGetSymbolAddress((void**)&cursor,  g_cursor);
    cudaGetSymbolAddress((void**)&bsums,   g_bsums);

    // --- CSR build (both edge directions) ---
    build_csr(ei_pa, ei_pa + NE, NP, NE, rptrP, ctgt_pa, counts, cursor, bsums);
    build_csr(ei_ap, ei_ap + NE, NA, NE, rptrA, ctgt_ap, counts, cursor, bsums);

    const int gemm64_blocks = (NP + 63) / 64;      // RPB = 64 for NOUT=64
    const int gemm32_blocks = (NP + 127) / 128;    // RPB = 128 for NOUT=32
    const int node_blocks   = (NP + 7) / 8;        // 8 warps per block

    // Input projection + ReLU
    gemm_kernel<DP, H, true><<<gemm64_blocks, 256>>>(x_P, fc1_P_w, fc1_P_b, featP, NP);
    gemm_kernel<DA, H, true><<<gemm64_blocks, 256>>>(x_A, fc1_A_w, fc1_A_b, featA, NA);

    for (int hop = 0; hop < 2; hop++) {
        const float* W    = fcs_w + (size_t)hop * H * H;
        const float* b    = fcs_b + (size_t)hop * H;
        const float* v1pa = a1_pa + (size_t)hop * H;
        const float* v2pa = a2_pa + (size_t)hop * H;
        const float* v1ap = a1_ap + (size_t)hop * H;
        const float* v2ap = a2_ap + (size_t)hop * H;

        gemm_kernel<H, H, false><<<gemm64_blocks, 256>>>(featP, W, b, xP, NP);
        gemm_kernel<H, H, false><<<gemm64_blocks, 256>>>(featA, W, b, xA, NA);

        // P is src of pa edges (a1_pa/a2_pa), dst of ap edges (a2_ap)
        nodeprep_kernel<<<node_blocks, 256>>>(xP, NP, v1pa, v2pa, v2ap, x1P, h1P, w2P);
        nodeprep_kernel<<<node_blocks, 256>>>(xA, NA, v1ap, v2ap, v2pa, x1A, h1A, w2A);

        // Aggregate + finalize (CSR, no atomics), writes feat for next layer
        csr_agg_kernel<<<node_blocks, 256>>>(rptrP, ctgt_pa, xP, x1P, w2P, h1A, xA, featP, NP);
        csr_agg_kernel<<<node_blocks, 256>>>(rptrA, ctgt_ap, xA, x1A, w2A, h1P, xP, featA, NA);
    }

    // Output head: [200000, 32]
    gemm_kernel<H, OUTD, false><<<gemm32_blocks, 256>>>(featP, fc2_w, fc2_b, out, NP);
}

// round 4
// speedup vs baseline: 1.0876x; 1.0876x over previous
#include <cuda_runtime.h>
#include <math.h>

#define NP 200000
#define NA 200000
#define NT (NP + NA)          // combined node space: P = [0,NP), A = [NP,NT)
#define NE 2000000
#define E2 (2 * NE)           // combined edge count
#define H  64
#define DP 128
#define DA 64
#define OUTD 32

// ---------------------------------------------------------------------------
// Device scratch (no cudaMalloc allowed)
// ---------------------------------------------------------------------------
__device__ float g_feat[(size_t)NT * H];   // layer features (P rows then A rows)
__device__ float g_x[(size_t)NT * H];      // fcs output
__device__ float g_x1[NT];
__device__ float g_h1[NT];
__device__ float g_w2[NT];
// Combined CSR over 400k nodes / 4M edges
__device__ int g_rptr[NT + 1];
__device__ int g_ctgt[E2];
__device__ int g_counts[NT + 1];
__device__ int g_cursor[NT + 1];
__device__ int g_bsums[512];

__device__ __forceinline__ float leaky02(float v) {
    return v > 0.0f ? v : 0.2f * v;
}

// ---------------------------------------------------------------------------
// CSR build kernels (combined edge space)
// ---------------------------------------------------------------------------
__global__ void zero_int_kernel(int* p, int n) {
    int i = blockIdx.x * blockDim.x + threadIdx.x;
    if (i < n) p[i] = 0;
}

// i < NE: pa edge (src = P idx). else: ap edge (src = NP + A idx)
__global__ void hist_kernel(const int* __restrict__ ei_pa, const int* __restrict__ ei_ap,
                            int* __restrict__ counts) {
    int i = blockIdx.x * blockDim.x + threadIdx.x;
    if (i < E2) {
        int s = (i < NE) ? ei_pa[i] : (NP + ei_ap[i - NE]);
        atomicAdd(&counts[s], 1);
    }
}

__global__ void block_sums_kernel(const int* __restrict__ c, int n, int* __restrict__ bs) {
    __shared__ int sd[1024];
    int i = blockIdx.x * 1024 + threadIdx.x;
    sd[threadIdx.x] = (i < n) ? c[i] : 0;
    __syncthreads();
    for (int o = 512; o; o >>= 1) {
        if (threadIdx.x < o) sd[threadIdx.x] += sd[threadIdx.x + o];
        __syncthreads();
    }
    if (threadIdx.x == 0) bs[blockIdx.x] = sd[0];
}

__global__ void scan_bs_kernel(int* bs, int nb) {   // nb <= 512
    __shared__ int s[512];
    int tid = threadIdx.x;
    int v = tid < nb ? bs[tid] : 0;
    s[tid] = v;
    __syncthreads();
    for (int o = 1; o < 512; o <<= 1) {
        int u = (tid >= o) ? s[tid - o] : 0;
        __syncthreads();
        s[tid] += u;
        __syncthreads();
    }
    if (tid < nb) bs[tid] = s[tid] - v;   // exclusive
}

__global__ void scan_final_kernel(const int* __restrict__ c, int n,
                                  const int* __restrict__ bs, int* __restrict__ rptr) {
    __shared__ int sd[1024];
    int i = blockIdx.x * 1024 + threadIdx.x;
    int v = (i < n) ? c[i] : 0;
    sd[threadIdx.x] = v;
    __syncthreads();
    for (int o = 1; o < 1024; o <<= 1) {
        int u = (threadIdx.x >= o) ? sd[threadIdx.x - o] : 0;
        __syncthreads();
        sd[threadIdx.x] += u;
        __syncthreads();
    }
    int excl = sd[threadIdx.x] - v + bs[blockIdx.x];
    if (i < n) rptr[i] = excl;
    if (i == n - 1) rptr[n] = excl + v;
}

__global__ void copy_int_kernel(const int* __restrict__ a, int* __restrict__ b, int n) {
    int i = blockIdx.x * blockDim.x + threadIdx.x;
    if (i < n) b[i] = a[i];
}

// Targets stored pre-offset into combined feature space:
//   pa edge: tgt = NP + A_idx ;  ap edge: tgt = P_idx
__global__ void scatter_kernel(const int* __restrict__ ei_pa, const int* __restrict__ ei_ap,
                               int* __restrict__ cursor, int* __restrict__ ctgt) {
    int i = blockIdx.x * blockDim.x + threadIdx.x;
    if (i < E2) {
        int s, t;
        if (i < NE) { s = ei_pa[i];            t = NP + ei_pa[NE + i]; }
        else        { s = NP + ei_ap[i - NE];  t = ei_ap[NE + (i - NE)]; }
        int pos = atomicAdd(&cursor[s], 1);
        ctgt[pos] = t;
    }
}

// ---------------------------------------------------------------------------
// GEMM: Y[N, NOUT] = act(X[N, K] @ W[K, NOUT] + b)
// 256 threads; each thread: 2 rows x 8 cols. W staged in shared memory.
// PREP: fused attention-prep epilogue (per-row dots + 8-lane reduce).
// ---------------------------------------------------------------------------
template<int K, int NOUT, bool RELU, bool PREP>
__global__ void __launch_bounds__(256)
gemm_kernel(const float* __restrict__ X, const float* __restrict__ W,
            const float* __restrict__ bias, float* __restrict__ Y, int N,
            const float* __restrict__ a1P, const float* __restrict__ a2P,
            const float* __restrict__ aoP,
            const float* __restrict__ a1A, const float* __restrict__ a2A,
            const float* __restrict__ aoA,
            float* __restrict__ x1o, float* __restrict__ h1o, float* __restrict__ w2o)
{
    constexpr int TPR = NOUT / 8;
    constexpr int RG  = 256 / TPR;
    constexpr int RPB = RG * 2;

    __shared__ float sW[K * NOUT];
    for (int i = threadIdx.x; i < K * NOUT; i += 256) sW[i] = W[i];
    __syncthreads();

    const int tg = threadIdx.x / TPR;
    const int cg = threadIdx.x % TPR;
    const int r0 = blockIdx.x * RPB + tg * 2;
    const int c0 = cg * 8;

    float acc[2][8];
    #pragma unroll
    for (int c = 0; c < 8; c++) {
        float bv = bias[c0 + c];
        acc[0][c] = bv;
        acc[1][c] = bv;
    }

    int rr[2];
    #pragma unroll
    for (int r = 0; r < 2; r++) {
        int q = r0 + r;
        rr[r] = q < N ? q : (N - 1);
    }

    #pragma unroll 2
    for (int k4 = 0; k4 < K / 4; k4++) {
        const int kb = k4 * 4;
        float wv[4][8];
        #pragma unroll
        for (int kk = 0; kk < 4; kk++) {
            float4 wa = *(const float4*)(&sW[(kb + kk) * NOUT + c0]);
            float4 wb = *(const float4*)(&sW[(kb + kk) * NOUT + c0 + 4]);
            wv[kk][0] = wa.x; wv[kk][1] = wa.y; wv[kk][2] = wa.z; wv[kk][3] = wa.w;
            wv[kk][4] = wb.x; wv[kk][5] = wb.y; wv[kk][6] = wb.z; wv[kk][7] = wb.w;
        }
        #pragma unroll
        for (int r = 0; r < 2; r++) {
            float4 xv = *(const float4*)(X + (size_t)rr[r] * K + kb);
            float xs[4] = {xv.x, xv.y, xv.z, xv.w};
            #pragma unroll
            for (int kk = 0; kk < 4; kk++)
                #pragma unroll
                for (int c = 0; c < 8; c++)
                    acc[r][c] += xs[kk] * wv[kk][c];
        }
    }

    #pragma unroll
    for (int r = 0; r < 2; r++) {
        int q = r0 + r;
        if (q < N) {
            float4 va, vb;
            if (RELU) {
                va = make_float4(fmaxf(acc[r][0],0.f), fmaxf(acc[r][1],0.f),
                                 fmaxf(acc[r][2],0.f), fmaxf(acc[r][3],0.f));
                vb = make_float4(fmaxf(acc[r][4],0.f), fmaxf(acc[r][5],0.f),
                                 fmaxf(acc[r][6],0.f), fmaxf(acc[r][7],0.f));
            } else {
                va = make_float4(acc[r][0], acc[r][1], acc[r][2], acc[r][3]);
                vb = make_float4(acc[r][4], acc[r][5], acc[r][6], acc[r][7]);
            }
            *(float4*)(Y + (size_t)q * NOUT + c0)     = va;
            *(float4*)(Y + (size_t)q * NOUT + c0 + 4) = vb;
        }
    }

    if (PREP) {
        // Rows r0, r0+1 never straddle NP (NP even, r0 even)
        const bool isP = (r0 < NP);
        const float* v1 = isP ? a1P : a1A;
        const float* v2 = isP ? a2P : a2A;
        const float* v3 = isP ? aoP : aoA;
        float s1[8], s2[8], s3[8];
        #pragma unroll
        for (int c = 0; c < 8; c += 4) {
            *(float4*)(s1 + c) = *(const float4*)(v1 + c0 + c);
            *(float4*)(s2 + c) = *(const float4*)(v2 + c0 + c);
            *(float4*)(s3 + c) = *(const float4*)(v3 + c0 + c);
        }
        #pragma unroll
        for (int r = 0; r < 2; r++) {
            float p1 = 0.f, p2 = 0.f, p3 = 0.f;
            #pragma unroll
            for (int c = 0; c < 8; c++) {
                p1 += acc[r][c] * s1[c];
                p2 += acc[r][c] * s2[c];
                p3 += acc[r][c] * s3[c];
            }
            #pragma unroll
            for (int o = 4; o; o >>= 1) {
                p1 += __shfl_xor_sync(0xFFFFFFFFu, p1, o);
                p2 += __shfl_xor_sync(0xFFFFFFFFu, p2, o);
                p3 += __shfl_xor_sync(0xFFFFFFFFu, p3, o);
            }
            int q = r0 + r;
            if (cg == 0 && q < N) {
                x1o[q] = p1;
                h1o[q] = p3;
                w2o[q] = __expf(leaky02(p1 + p2));
            }
        }
    }
}

// ---------------------------------------------------------------------------
// CSR aggregation + finalize: one warp per source node (combined space).
//   acc = w2*x + sum_e w1_e * x[t_e];  div = w2 + sum w1 ; out = elu(acc/div)
// 2-way edge unroll with independent accumulator pairs.
// ---------------------------------------------------------------------------
__global__ void __launch_bounds__(256)
csr_agg_kernel(const int* __restrict__ rptr, const int* __restrict__ ctgt,
               const float* __restrict__ x, const float* __restrict__ x1,
               const float* __restrict__ w2arr, const float* __restrict__ h1,
               float* __restrict__ outfeat, int N)
{
    int s = (blockIdx.x * blockDim.x + threadIdx.x) >> 5;
    int lane = threadIdx.x & 31;
    if (s >= N) return;

    int beg = rptr[s];
    int end = rptr[s + 1];
    float x1s = x1[s];
    float w2  = w2arr[s];

    float2 xv = *(const float2*)(x + (size_t)s * H + lane * 2);
    float2 accA; accA.x = w2 * xv.x; accA.y = w2 * xv.y;
    float2 accB; accB.x = 0.f; accB.y = 0.f;
    float divA = w2, divB = 0.f;

    for (int base = beg; base < end; base += 32) {
        int myIdx = base + lane;
        int t = 0; float h1t = 0.0f;
        if (myIdx < end) {
            t = ctgt[myIdx];
            h1t = h1[t];
        }
        int cnt = min(32, end - base);
        int i = 0;
        for (; i + 1 < cnt; i += 2) {
            int   t0 = __shfl_sync(0xFFFFFFFFu, t, i);
            float g0 = __shfl_sync(0xFFFFFFFFu, h1t, i);
            int   t1 = __shfl_sync(0xFFFFFFFFu, t, i + 1);
            float g1 = __shfl_sync(0xFFFFFFFFu, h1t, i + 1);
            float w0 = __expf(leaky02(x1s + g0));
            float w1 = __expf(leaky02(x1s + g1));
            float2 hv0 = *(const float2*)(x + (size_t)t0 * H + lane * 2);
            float2 hv1 = *(const float2*)(x + (size_t)t1 * H + lane * 2);
            accA.x += w0 * hv0.x; accA.y += w0 * hv0.y; divA += w0;
            accB.x += w1 * hv1.x; accB.y += w1 * hv1.y; divB += w1;
        }
        if (i < cnt) {
            int   t0 = __shfl_sync(0xFFFFFFFFu, t, i);
            float g0 = __shfl_sync(0xFFFFFFFFu, h1t, i);
            float w0 = __expf(leaky02(x1s + g0));
            float2 hv0 = *(const float2*)(x + (size_t)t0 * H + lane * 2);
            accA.x += w0 * hv0.x; accA.y += w0 * hv0.y; divA += w0;
        }
    }

    float divv = divA + divB;
    float inv = 1.0f / divv;
    float vx = (accA.x + accB.x) * inv;
    float vy = (accA.y + accB.y) * inv;
    vx = vx > 0.0f ? vx : (__expf(vx) - 1.0f);
    vy = vy > 0.0f ? vy : (__expf(vy) - 1.0f);
    float2 o; o.x = vx; o.y = vy;
    *(float2*)(outfeat + (size_t)s * H + lane * 2) = o;
}

// ---------------------------------------------------------------------------
// Launch
// ---------------------------------------------------------------------------
extern "C" void kernel_launch(void* const* d_in, const int* in_sizes, int n_in,
                              void* d_out, int out_size)
{
    const float* x_P     = (const float*)d_in[0];
    const float* x_A     = (const float*)d_in[1];
    const int*   ei_pa   = (const int*)d_in[2];
    const int*   ei_ap   = (const int*)d_in[3];
    const float* fc1_P_w = (const float*)d_in[4];
    const float* fc1_P_b = (const float*)d_in[5];
    const float* fc1_A_w = (const float*)d_in[6];
    const float* fc1_A_b = (const float*)d_in[7];
    const float* fcs_w   = (const float*)d_in[8];
    const float* fcs_b   = (const float*)d_in[9];
    const float* a1_pa   = (const float*)d_in[10];
    const float* a2_pa   = (const float*)d_in[11];
    const float* a1_ap   = (const float*)d_in[12];
    const float* a2_ap   = (const float*)d_in[13];
    const float* fc2_w   = (const float*)d_in[14];
    const float* fc2_b   = (const float*)d_in[15];
    float* out = (float*)d_out;

    float *feat, *x, *x1, *h1, *w2;
    int *rptr, *ctgt, *counts, *cursor, *bsums;
    cudaGetSymbolAddress((void**)&feat,   g_feat);
    cudaGetSymbolAddress((void**)&x,      g_x);
    cudaGetSymbolAddress((void**)&x1,     g_x1);
    cudaGetSymbolAddress((void**)&h1,     g_h1);
    cudaGetSymbolAddress((void**)&w2,     g_w2);
    cudaGetSymbolAddress((void**)&rptr,   g_rptr);
    cudaGetSymbolAddress((void**)&ctgt,   g_ctgt);
    cudaGetSymbolAddress((void**)&counts, g_counts);
    cudaGetSymbolAddress((void**)&cursor, g_cursor);
    cudaGetSymbolAddress((void**)&bsums,  g_bsums);

    const int NB = (NT + 1023) / 1024;                 // 391 scan blocks
    const int gemmP_blocks   = (NP + 63) / 64;
    const int gemmT_blocks   = (NT + 63) / 64;
    const int gemm32_blocks  = (NP + 127) / 128;
    const int agg_blocks     = (NT + 7) / 8;

    // --- CSR build interleaved with independent GEMMs (profiling-friendly order) ---
    zero_int_kernel<<<(NT + 255) / 256, 256>>>(counts, NT);
    hist_kernel<<<(E2 + 255) / 256, 256>>>(ei_pa, ei_ap, counts);
    block_sums_kernel<<<NB, 1024>>>(counts, NT, bsums);

    // Input projection + ReLU (feat: P rows then A rows)
    gemm_kernel<DP, H, true, false><<<gemmP_blocks, 256>>>(
        x_P, fc1_P_w, fc1_P_b, feat, NP,
        nullptr,nullptr,nullptr,nullptr,nullptr,nullptr,nullptr,nullptr,nullptr);
    gemm_kernel<DA, H, true, false><<<gemmP_blocks, 256>>>(
        x_A, fc1_A_w, fc1_A_b, feat + (size_t)NP * H, NA,
        nullptr,nullptr,nullptr,nullptr,nullptr,nullptr,nullptr,nullptr,nullptr);

    // hop 0 fcs GEMM + fused attention prep (independent of CSR)
    gemm_kernel<H, H, false, true><<<gemmT_blocks, 256>>>(
        feat, fcs_w, fcs_b, x, NT,
        a1_pa, a2_pa, a2_ap,          // P rows: src of pa, dst of ap
        a1_ap, a2_ap, a2_pa,          // A rows: src of ap, dst of pa
        x1, h1, w2);

    scan_bs_kernel<<<1, 512>>>(bsums, NB);
    scan_final_kernel<<<NB, 1024>>>(counts, NT, bsums, rptr);
    copy_int_kernel<<<(NT + 255) / 256, 256>>>(rptr, cursor, NT);
    scatter_kernel<<<(E2 + 255) / 256, 256>>>(ei_pa, ei_ap, cursor, ctgt);

    // hop 0 aggregation + elu -> feat
    csr_agg_kernel<<<agg_blocks, 256>>>(rptr, ctgt, x, x1, w2, h1, feat, NT);

    // hop 1
    gemm_kernel<H, H, false, true><<<gemmT_blocks, 256>>>(
        feat, fcs_w + (size_t)H * H, fcs_b + H, x, NT,
        a1_pa + H, a2_pa + H, a2_ap + H,
        a1_ap + H, a2_ap + H, a2_pa + H,
        x1, h1, w2);
    csr_agg_kernel<<<agg_blocks, 256>>>(rptr, ctgt, x, x1, w2, h1, feat, NT);

    // Output head over P rows
    gemm_kernel<H, OUTD, false, false><<<gemm32_blocks, 256>>>(
        feat, fc2_w, fc2_b, out, NP,
        nullptr,nullptr,nullptr,nullptr,nullptr,nullptr,nullptr,nullptr,nullptr);
}

// round 6
// speedup vs baseline: 1.6125x; 1.4826x over previous
#include <cuda_runtime.h>
#include <math.h>

#define NP 200000
#define NA 200000
#define NT (NP + NA)          // combined node space: P = [0,NP), A = [NP,NT)
#define NE 2000000
#define E2 (2 * NE)
#define H  64
#define DP 128
#define DA 64
#define OUTD 32

// ---------------------------------------------------------------------------
// Device scratch (no cudaMalloc allowed)
// ---------------------------------------------------------------------------
__device__ float g_feat[(size_t)NT * H];
__device__ float g_x[(size_t)NT * H];
__device__ float g_x1[NT];
__device__ float g_h1[NT];
__device__ float g_w2[NT];
__device__ int g_rptr[NT + 1];
__device__ int g_ctgt[E2];
__device__ int g_counts[NT + 1];
__device__ int g_cursor[NT + 1];
__device__ int g_bsums[512];

__device__ __forceinline__ float leaky02(float v) {
    return v > 0.0f ? v : 0.2f * v;
}

// ---------------------------------------------------------------------------
// CSR build kernels (combined edge space)
// ---------------------------------------------------------------------------
__global__ void zero_int_kernel(int* p, int n) {
    int i = blockIdx.x * blockDim.x + threadIdx.x;
    if (i < n) p[i] = 0;
}

__global__ void hist_kernel(const int* __restrict__ ei_pa, const int* __restrict__ ei_ap,
                            int* __restrict__ counts) {
    int i = blockIdx.x * blockDim.x + threadIdx.x;
    if (i < E2) {
        int s = (i < NE) ? ei_pa[i] : (NP + ei_ap[i - NE]);
        atomicAdd(&counts[s], 1);
    }
}

__global__ void block_sums_kernel(const int* __restrict__ c, int n, int* __restrict__ bs) {
    __shared__ int sd[1024];
    int i = blockIdx.x * 1024 + threadIdx.x;
    sd[threadIdx.x] = (i < n) ? c[i] : 0;
    __syncthreads();
    for (int o = 512; o; o >>= 1) {
        if (threadIdx.x < o) sd[threadIdx.x] += sd[threadIdx.x + o];
        __syncthreads();
    }
    if (threadIdx.x == 0) bs[blockIdx.x] = sd[0];
}

__global__ void scan_bs_kernel(int* bs, int nb) {   // nb <= 512
    __shared__ int s[512];
    int tid = threadIdx.x;
    int v = tid < nb ? bs[tid] : 0;
    s[tid] = v;
    __syncthreads();
    for (int o = 1; o < 512; o <<= 1) {
        int u = (tid >= o) ? s[tid - o] : 0;
        __syncthreads();
        s[tid] += u;
        __syncthreads();
    }
    if (tid < nb) bs[tid] = s[tid] - v;
}

__global__ void scan_final_kernel(const int* __restrict__ c, int n,
                                  const int* __restrict__ bs, int* __restrict__ rptr) {
    __shared__ int sd[1024];
    int i = blockIdx.x * 1024 + threadIdx.x;
    int v = (i < n) ? c[i] : 0;
    sd[threadIdx.x] = v;
    __syncthreads();
    for (int o = 1; o < 1024; o <<= 1) {
        int u = (threadIdx.x >= o) ? sd[threadIdx.x - o] : 0;
        __syncthreads();
        sd[threadIdx.x] += u;
        __syncthreads();
    }
    int excl = sd[threadIdx.x] - v + bs[blockIdx.x];
    if (i < n) rptr[i] = excl;
    if (i == n - 1) rptr[n] = excl + v;
}

__global__ void copy_int_kernel(const int* __restrict__ a, int* __restrict__ b, int n) {
    int i = blockIdx.x * blockDim.x + threadIdx.x;
    if (i < n) b[i] = a[i];
}

__global__ void scatter_kernel(const int* __restrict__ ei_pa, const int* __restrict__ ei_ap,
                               int* __restrict__ cursor, int* __restrict__ ctgt) {
    int i = blockIdx.x * blockDim.x + threadIdx.x;
    if (i < E2) {
        int s, t;
        if (i < NE) { s = ei_pa[i];            t = NP + ei_pa[NE + i]; }
        else        { s = NP + ei_ap[i - NE];  t = ei_ap[NE + (i - NE)]; }
        int pos = atomicAdd(&cursor[s], 1);
        ctgt[pos] = t;
    }
}

// ---------------------------------------------------------------------------
// Register-blocked SGEMM: Y[N, BN] = act(X[N, K] @ W[K, BN] + b)
// BM=128, BK=16, 128 threads, thread tile TM=8 x TN=BN/8.
// X staged transposed in smem; W tile contiguous (BN = full row width).
// PREP: fused attention-prep epilogue.
// ---------------------------------------------------------------------------
template<int K, int BN, bool RELU, bool PREP>
__global__ void __launch_bounds__(128)
gemm_kernel(const float* __restrict__ X, const float* __restrict__ W,
            const float* __restrict__ bias, float* __restrict__ Y, int N,
            const float* __restrict__ a1P, const float* __restrict__ a2P,
            const float* __restrict__ aoP,
            const float* __restrict__ a1A, const float* __restrict__ a2A,
            const float* __restrict__ aoA,
            float* __restrict__ x1o, float* __restrict__ h1o, float* __restrict__ w2o)
{
    constexpr int BM = 128;
    constexpr int BK = 16;
    constexpr int TM = 8;
    constexpr int TN = BN / 8;          // 8 for BN=64, 4 for BN=32

    __shared__ float sX[BK][BM];
    __shared__ float sW[BK][BN];

    const int tid = threadIdx.x;
    const int tr  = tid >> 3;           // 0..15 (row group)
    const int tc  = tid & 7;            // 0..7  (col group)
    const int r0  = blockIdx.x * BM;

    float acc[TM][TN];
    #pragma unroll
    for (int j = 0; j < TN; j++) {
        float bv = bias[tc * TN + j];
        #pragma unroll
        for (int r = 0; r < TM; r++) acc[r][j] = bv;
    }

    // Row this thread stages into smem (clamped; writes guarded later)
    int gr = r0 + tid;
    if (gr >= N) gr = N - 1;
    const float* xrow = X + (size_t)gr * K;

    for (int k0 = 0; k0 < K; k0 += BK) {
        // Stage X tile transposed: thread loads 16 values of its row.
        float4 v0 = *(const float4*)(xrow + k0);
        float4 v1 = *(const float4*)(xrow + k0 + 4);
        float4 v2 = *(const float4*)(xrow + k0 + 8);
        float4 v3 = *(const float4*)(xrow + k0 + 12);
        sX[ 0][tid] = v0.x; sX[ 1][tid] = v0.y; sX[ 2][tid] = v0.z; sX[ 3][tid] = v0.w;
        sX[ 4][tid] = v1.x; sX[ 5][tid] = v1.y; sX[ 6][tid] = v1.z; sX[ 7][tid] = v1.w;
        sX[ 8][tid] = v2.x; sX[ 9][tid] = v2.y; sX[10][tid] = v2.z; sX[11][tid] = v2.w;
        sX[12][tid] = v3.x; sX[13][tid] = v3.y; sX[14][tid] = v3.z; sX[15][tid] = v3.w;

        // Stage W tile (contiguous BK*BN floats starting at k0*BN)
        const float4* wsrc = (const float4*)(W + (size_t)k0 * BN);
        float4* wdst = (float4*)&sW[0][0];
        #pragma unroll
        for (int i = tid; i < BK * BN / 4; i += 128) wdst[i] = wsrc[i];

        __syncthreads();

        #pragma unroll
        for (int kk = 0; kk < BK; kk++) {
            float xr[TM];
            *(float4*)(xr)     = *(const float4*)(&sX[kk][tr * TM]);
            *(float4*)(xr + 4) = *(const float4*)(&sX[kk][tr * TM + 4]);
            float wr[TN];
            #pragma unroll
            for (int j = 0; j < TN; j += 4)
                *(float4*)(wr + j) = *(const float4*)(&sW[kk][tc * TN + j]);
            #pragma unroll
            for (int r = 0; r < TM; r++)
                #pragma unroll
                for (int j = 0; j < TN; j++)
                    acc[r][j] += xr[r] * wr[j];
        }
        __syncthreads();
    }

    // Epilogue: activation + store
    #pragma unroll
    for (int r = 0; r < TM; r++) {
        int q = r0 + tr * TM + r;
        if (q < N) {
            if (RELU) {
                #pragma unroll
                for (int j = 0; j < TN; j++) acc[r][j] = fmaxf(acc[r][j], 0.0f);
            }
            #pragma unroll
            for (int j = 0; j < TN; j += 4)
                *(float4*)(Y + (size_t)q * BN + tc * TN + j) = *(float4*)(&acc[r][j]);
        }
    }

    if (PREP) {
        // All 8 rows of this thread are on one side of NP (NP % 8 == 0, tiles 8-aligned)
        const int rowbase = r0 + tr * TM;
        const bool isP = (rowbase < NP);
        const float* v1 = isP ? a1P : a1A;
        const float* v2 = isP ? a2P : a2A;
        const float* v3 = isP ? aoP : aoA;
        float s1[TN], s2[TN], s3[TN];
        #pragma unroll
        for (int j = 0; j < TN; j += 4) {
            *(float4*)(s1 + j) = *(const float4*)(v1 + tc * TN + j);
            *(float4*)(s2 + j) = *(const float4*)(v2 + tc * TN + j);
            *(float4*)(s3 + j) = *(const float4*)(v3 + tc * TN + j);
        }
        #pragma unroll
        for (int r = 0; r < TM; r++) {
            float p1 = 0.f, p2 = 0.f, p3 = 0.f;
            #pragma unroll
            for (int j = 0; j < TN; j++) {
                p1 += acc[r][j] * s1[j];
                p2 += acc[r][j] * s2[j];
                p3 += acc[r][j] * s3[j];
            }
            #pragma unroll
            for (int o = 4; o; o >>= 1) {
                p1 += __shfl_xor_sync(0xFFFFFFFFu, p1, o);
                p2 += __shfl_xor_sync(0xFFFFFFFFu, p2, o);
                p3 += __shfl_xor_sync(0xFFFFFFFFu, p3, o);
            }
            int q = rowbase + r;
            if (tc == 0 && q < N) {
                x1o[q] = p1;
                h1o[q] = p3;
                w2o[q] = __expf(leaky02(p1 + p2));
            }
        }
    }
}

// ---------------------------------------------------------------------------
// CSR aggregation + finalize: one warp per source node (combined space).
// ---------------------------------------------------------------------------
__global__ void __launch_bounds__(256)
csr_agg_kernel(const int* __restrict__ rptr, const int* __restrict__ ctgt,
               const float* __restrict__ x, const float* __restrict__ x1,
               const float* __restrict__ w2arr, const float* __restrict__ h1,
               float* __restrict__ outfeat, int N)
{
    int s = (blockIdx.x * blockDim.x + threadIdx.x) >> 5;
    int lane = threadIdx.x & 31;
    if (s >= N) return;

    int beg = rptr[s];
    int end = rptr[s + 1];
    float x1s = x1[s];
    float w2  = w2arr[s];

    float2 xv = *(const float2*)(x + (size_t)s * H + lane * 2);
    float2 accA; accA.x = w2 * xv.x; accA.y = w2 * xv.y;
    float2 accB; accB.x = 0.f; accB.y = 0.f;
    float divA = w2, divB = 0.f;

    for (int base = beg; base < end; base += 32) {
        int myIdx = base + lane;
        int t = 0; float h1t = 0.0f;
        if (myIdx < end) {
            t = ctgt[myIdx];
            h1t = h1[t];
        }
        int cnt = min(32, end - base);
        int i = 0;
        for (; i + 1 < cnt; i += 2) {
            int   t0 = __shfl_sync(0xFFFFFFFFu, t, i);
            float g0 = __shfl_sync(0xFFFFFFFFu, h1t, i);
            int   t1 = __shfl_sync(0xFFFFFFFFu, t, i + 1);
            float g1 = __shfl_sync(0xFFFFFFFFu, h1t, i + 1);
            float w0 = __expf(leaky02(x1s + g0));
            float w1 = __expf(leaky02(x1s + g1));
            float2 hv0 = *(const float2*)(x + (size_t)t0 * H + lane * 2);
            float2 hv1 = *(const float2*)(x + (size_t)t1 * H + lane * 2);
            accA.x += w0 * hv0.x; accA.y += w0 * hv0.y; divA += w0;
            accB.x += w1 * hv1.x; accB.y += w1 * hv1.y; divB += w1;
        }
        if (i < cnt) {
            int   t0 = __shfl_sync(0xFFFFFFFFu, t, i);
            float g0 = __shfl_sync(0xFFFFFFFFu, h1t, i);
            float w0 = __expf(leaky02(x1s + g0));
            float2 hv0 = *(const float2*)(x + (size_t)t0 * H + lane * 2);
            accA.x += w0 * hv0.x; accA.y += w0 * hv0.y; divA += w0;
        }
    }

    float divv = divA + divB;
    float inv = 1.0f / divv;
    float vx = (accA.x + accB.x) * inv;
    float vy = (accA.y + accB.y) * inv;
    vx = vx > 0.0f ? vx : (__expf(vx) - 1.0f);
    vy = vy > 0.0f ? vy : (__expf(vy) - 1.0f);
    float2 o; o.x = vx; o.y = vy;
    *(float2*)(outfeat + (size_t)s * H + lane * 2) = o;
}

// ---------------------------------------------------------------------------
// Launch
// ---------------------------------------------------------------------------
extern "C" void kernel_launch(void* const* d_in, const int* in_sizes, int n_in,
                              void* d_out, int out_size)
{
    const float* x_P     = (const float*)d_in[0];
    const float* x_A     = (const float*)d_in[1];
    const int*   ei_pa   = (const int*)d_in[2];
    const int*   ei_ap   = (const int*)d_in[3];
    const float* fc1_P_w = (const float*)d_in[4];
    const float* fc1_P_b = (const float*)d_in[5];
    const float* fc1_A_w = (const float*)d_in[6];
    const float* fc1_A_b = (const float*)d_in[7];
    const float* fcs_w   = (const float*)d_in[8];
    const float* fcs_b   = (const float*)d_in[9];
    const float* a1_pa   = (const float*)d_in[10];
    const float* a2_pa   = (const float*)d_in[11];
    const float* a1_ap   = (const float*)d_in[12];
    const float* a2_ap   = (const float*)d_in[13];
    const float* fc2_w   = (const float*)d_in[14];
    const float* fc2_b   = (const float*)d_in[15];
    float* out = (float*)d_out;

    float *feat, *x, *x1, *h1, *w2;
    int *rptr, *ctgt, *counts, *cursor, *bsums;
    cudaGetSymbolAddress((void**)&feat,   g_feat);
    cudaGetSymbolAddress((void**)&x,      g_x);
    cudaGetSymbolAddress((void**)&x1,     g_x1);
    cudaGetSymbolAddress((void**)&h1,     g_h1);
    cudaGetSymbolAddress((void**)&w2,     g_w2);
    cudaGetSymbolAddress((void**)&rptr,   g_rptr);
    cudaGetSymbolAddress((void**)&ctgt,   g_ctgt);
    cudaGetSymbolAddress((void**)&counts, g_counts);
    cudaGetSymbolAddress((void**)&cursor, g_cursor);
    cudaGetSymbolAddress((void**)&bsums,  g_bsums);

    const int NB = (NT + 1023) / 1024;
    const int gemmP_blocks  = (NP + 127) / 128;
    const int gemmT_blocks  = (NT + 127) / 128;
    const int agg_blocks    = (NT + 7) / 8;

    // --- CSR build interleaved with independent GEMMs ---
    zero_int_kernel<<<(NT + 255) / 256, 256>>>(counts, NT);
    hist_kernel<<<(E2 + 255) / 256, 256>>>(ei_pa, ei_ap, counts);
    block_sums_kernel<<<NB, 1024>>>(counts, NT, bsums);

    gemm_kernel<DP, H, true, false><<<gemmP_blocks, 128>>>(
        x_P, fc1_P_w, fc1_P_b, feat, NP,
        nullptr,nullptr,nullptr,nullptr,nullptr,nullptr,nullptr,nullptr,nullptr);
    gemm_kernel<DA, H, true, false><<<gemmP_blocks, 128>>>(
        x_A, fc1_A_w, fc1_A_b, feat + (size_t)NP * H, NA,
        nullptr,nullptr,nullptr,nullptr,nullptr,nullptr,nullptr,nullptr,nullptr);

    gemm_kernel<H, H, false, true><<<gemmT_blocks, 128>>>(
        feat, fcs_w, fcs_b, x, NT,
        a1_pa, a2_pa, a2_ap,
        a1_ap, a2_ap, a2_pa,
        x1, h1, w2);

    scan_bs_kernel<<<1, 512>>>(bsums, NB);
    scan_final_kernel<<<NB, 1024>>>(counts, NT, bsums, rptr);
    copy_int_kernel<<<(NT + 255) / 256, 256>>>(rptr, cursor, NT);
    scatter_kernel<<<(E2 + 255) / 256, 256>>>(ei_pa, ei_ap, cursor, ctgt);

    csr_agg_kernel<<<agg_blocks, 256>>>(rptr, ctgt, x, x1, w2, h1, feat, NT);

    gemm_kernel<H, H, false, true><<<gemmT_blocks, 128>>>(
        feat, fcs_w + (size_t)H * H, fcs_b + H, x, NT,
        a1_pa + H, a2_pa + H, a2_ap + H,
        a1_ap + H, a2_ap + H, a2_pa + H,
        x1, h1, w2);
    csr_agg_kernel<<<agg_blocks, 256>>>(rptr, ctgt, x, x1, w2, h1, feat, NT);

    gemm_kernel<H, OUTD, false, false><<<gemmP_blocks, 128>>>(
        feat, fc2_w, fc2_b, out, NP,
        nullptr,nullptr,nullptr,nullptr,nullptr,nullptr,nullptr,nullptr,nullptr);
}